// round 12
// baseline (speedup 1.0000x reference)
#include <cuda_runtime.h>
#include <stdint.h>

// SparseActivation: per-row top-k (k=204) by |x| over D=2048, out = x*mask*(D/k).
// ONE WARP PER ROW, no __syncthreads.
//  Pass A (ballot-free): 16 LDG.128/lane (unroll 8); each lane appends abs-bit
//          candidates (key >= bits(1.45f)) to a PRIVATE scalar smem column
//          (33-word stride, conflict-free). Then one warp scan of counts and a
//          per-lane copy into a compacted buffer. Overflow (cnt>33) or
//          nc outside [204,416] -> exact global-bisect fallback (ignores smem;
//          spills stay inside this warp's region, so no cross-warp corruption).
//  Pass B: register-cached (CPL=13) warp MSB-first bisection, early exit
//          (rank==group -> min, rank==1 -> max), REDUX reductions. (R11-proven.)
//  Pass C: re-read row (L2 hot, unroll 4); float compare |v|>=T_f common path,
//          exact lowest-index-first tie path. Streaming stores. (R11-proven.)

#define DDIM          2048
#define KSEL          204u
#define WARPS_PER_CTA 8
#define THREADS       (WARPS_PER_CTA * 32)
#define NCHUNK        16            // 16 float4 per lane = 2048 floats per warp
#define CAP           416           // compacted capacity = 13 per lane
#define CPL           13
#define COLW          33            // private column stride (scalar conflict-free)
#define WARP_COLS     (COLW * 32 + COLW)  // + spare column: lane31 spill stays in-warp
#define KLO_BITS      0x3FB9999Au   // __float_as_uint(1.45f)

static __device__ __forceinline__ uint32_t absbits(float f) {
    return __float_as_uint(f) & 0x7fffffffu;
}

__global__ __launch_bounds__(THREADS)
void sparse_act_kernel(const float* __restrict__ x, float* __restrict__ out)
{
    __shared__ uint32_t cols[WARPS_PER_CTA * WARP_COLS];
    __shared__ uint32_t comp[WARPS_PER_CTA][CAP];

    const int lane = threadIdx.x & 31;
    const int warp = threadIdx.x >> 5;
    const size_t row = (size_t)blockIdx.x * WARPS_PER_CTA + warp;

    const float4* __restrict__ xr   = reinterpret_cast<const float4*>(x + row * (size_t)DDIM);
    float4* __restrict__       orow = reinterpret_cast<float4*>(out + row * (size_t)DDIM);
    uint32_t* __restrict__ mycol = &cols[warp * WARP_COLS + lane * COLW];
    uint32_t* __restrict__ wbuf  = comp[warp];

    // ── Pass A: per-lane private append (no ballots) ──
    uint32_t cnt = 0;
#pragma unroll 8
    for (int i = 0; i < NCHUNK; ++i) {
        const float4 v = xr[i * 32 + lane];
        const uint32_t k[4] = { absbits(v.x), absbits(v.y), absbits(v.z), absbits(v.w) };
#pragma unroll
        for (int j = 0; j < 4; ++j) {
            if (k[j] >= KLO_BITS) { mycol[cnt] = k[j]; ++cnt; }
        }
    }
    const uint32_t nc  = __reduce_add_sync(0xffffffffu, cnt);
    const bool     ofl = __ballot_sync(0xffffffffu, cnt > (uint32_t)COLW) != 0u;

    uint32_t T, need, cntEq;

    if (!ofl && nc >= KSEL && nc <= CAP) {
        // ── compact: exclusive scan of counts, per-lane copy into comp ──
        uint32_t incl = cnt;
#pragma unroll
        for (int off = 1; off < 32; off <<= 1) {
            const uint32_t t = __shfl_up_sync(0xffffffffu, incl, off);
            if (lane >= off) incl += t;
        }
        uint32_t o = incl - cnt;
#pragma unroll 4
        for (uint32_t t = 0; t < cnt; ++t) wbuf[o + t] = mycol[t];
        __syncwarp();

        // ── Pass B: register-resident candidates, early-exit bisection ──
        uint32_t c[CPL];
#pragma unroll
        for (int j = 0; j < CPL; ++j) {
            const uint32_t idx = (uint32_t)lane + 32u * j;   // < CAP always
            const uint32_t t = wbuf[idx];                    // already abs bits
            c[j] = (idx < nc) ? t : 0xffffffffu;             // sentinel (never matches)
        }
        int b = 31;
        uint32_t p = 0u, kk = KSEL, g = nc;
        while (true) {
            if (kk == g) {            // take whole group -> T = group min
                uint32_t m = 0xffffffffu;
#pragma unroll
                for (int j = 0; j < CPL; ++j)
                    if ((c[j] >> b) == (p >> b)) m = min(m, c[j]);
                T = __reduce_min_sync(0xffffffffu, m);
                uint32_t e = 0;
#pragma unroll
                for (int j = 0; j < CPL; ++j) e += (c[j] == T) ? 1u : 0u;
                need  = __reduce_add_sync(0xffffffffu, e);
                cntEq = need;
                break;
            }
            if (kk == 1u) {           // T = group max
                uint32_t m = 0u;
#pragma unroll
                for (int j = 0; j < CPL; ++j)
                    if ((c[j] >> b) == (p >> b)) m = max(m, c[j]);
                T = __reduce_max_sync(0xffffffffu, m);
                uint32_t e = 0;
#pragma unroll
                for (int j = 0; j < CPL; ++j) e += (c[j] == T) ? 1u : 0u;
                cntEq = __reduce_add_sync(0xffffffffu, e);
                need  = 1u;
                break;
            }
            --b;
            const uint32_t hi = (p >> b) | 1u;
            uint32_t c2 = 0;
#pragma unroll
            for (int j = 0; j < CPL; ++j) c2 += ((c[j] >> b) == hi) ? 1u : 0u;
            c2 = __reduce_add_sync(0xffffffffu, c2);
            if (c2 >= kk) { p |= (1u << b); g = c2; }
            else          { kk -= c2;       g -= c2; }
            if (b == 0) { T = p; need = kk; cntEq = g; break; }
        }
    } else {
        // ── exact fallback (~never taken): bisect over full row from global ──
        uint32_t p = 0u, kk = KSEL, g = (uint32_t)DDIM;
        for (int b = 30; b >= 0; --b) {
            const uint32_t hi = (p >> b) | 1u;
            uint32_t c2 = 0;
            for (int i = 0; i < NCHUNK; ++i) {
                const float4 v = xr[i * 32 + lane];
                c2 += ((absbits(v.x) >> b) == hi) ? 1u : 0u;
                c2 += ((absbits(v.y) >> b) == hi) ? 1u : 0u;
                c2 += ((absbits(v.z) >> b) == hi) ? 1u : 0u;
                c2 += ((absbits(v.w) >> b) == hi) ? 1u : 0u;
            }
            c2 = __reduce_add_sync(0xffffffffu, c2);
            if (c2 >= kk) { p |= (1u << b); g = c2; }
            else          { kk -= c2;       g -= c2; }
        }
        T = p; need = kk; cntEq = g;
    }

    const bool rare = (need != cntEq);            // warp-uniform
    const float Tf  = __uint_as_float(T);         // positive; |v|>=Tf <=> absbits(v)>=T
    const float SCALE = (float)(2048.0 / 204.0);

    // ── Pass C: re-read (L2 hot), mask, scale, streaming store ──
    if (!rare) {
#pragma unroll 4
        for (int i = 0; i < NCHUNK; ++i) {
            const float4 v = xr[i * 32 + lane];
            float4 o;
            o.x = (fabsf(v.x) >= Tf) ? v.x * SCALE : 0.0f;
            o.y = (fabsf(v.y) >= Tf) ? v.y * SCALE : 0.0f;
            o.z = (fabsf(v.z) >= Tf) ? v.z * SCALE : 0.0f;
            o.w = (fabsf(v.w) >= Tf) ? v.w * SCALE : 0.0f;
            __stcs(&orow[i * 32 + lane], o);
        }
    } else {
        // exact lowest-index-first tie ranking (index = i*128 + lane*4 + j)
        uint32_t run = 0;
#pragma unroll 4
        for (int i = 0; i < NCHUNK; ++i) {
            const float4 v = xr[i * 32 + lane];
            const uint32_t k0 = absbits(v.x), k1 = absbits(v.y),
                           k2 = absbits(v.z), k3 = absbits(v.w);
            const uint32_t e0 = (k0 == T), e1 = (k1 == T),
                           e2 = (k2 == T), e3 = (k3 == T);
            uint32_t elane = e0 + e1 + e2 + e3;
            uint32_t incl = elane;
#pragma unroll
            for (int off = 1; off < 32; off <<= 1) {
                const uint32_t t = __shfl_up_sync(0xffffffffu, incl, off);
                if (lane >= off) incl += t;
            }
            uint32_t r = run + (incl - elane);
            float4 o;
            o.x = ((k0 > T) || (e0 && r < need)) ? v.x * SCALE : 0.0f; r += e0;
            o.y = ((k1 > T) || (e1 && r < need)) ? v.y * SCALE : 0.0f; r += e1;
            o.z = ((k2 > T) || (e2 && r < need)) ? v.z * SCALE : 0.0f; r += e2;
            o.w = ((k3 > T) || (e3 && r < need)) ? v.w * SCALE : 0.0f;
            run += __shfl_sync(0xffffffffu, incl, 31);
            __stcs(&orow[i * 32 + lane], o);
        }
    }
}

extern "C" void kernel_launch(void* const* d_in, const int* in_sizes, int n_in,
                              void* d_out, int out_size)
{
    const float* x = (const float*)d_in[0];
    float* out = (float*)d_out;
    const int rows   = in_sizes[0] / DDIM;            // 16384
    const int blocks = rows / WARPS_PER_CTA;          // 2048
    sparse_act_kernel<<<blocks, THREADS>>>(x, out);
}